// round 1
// baseline (speedup 1.0000x reference)
#include <cuda_runtime.h>

// Problem constants (shapes fixed by the dataset)
static constexpr int NV   = 48;    // N
static constexpr int NP1  = 49;    // N+1
static constexpr int NB   = 98;    // 2N+2 merged bounds
static constexpr int MAXXP = 257;  // largest prop_sdist width
static constexpr int ROWS_PER_BLOCK = 8;
static constexpr int NSEG = 65536;

static constexpr float PW0 = 0.01f;
static constexpr float PW1 = 0.005f;

struct RowS {
    float sd[NP1];      // render_sdist row
    float w[NV];        // render_weights row
    float wn[NV];       // wnorm
    float bounds[NB];   // merged/sorted bounds
    float rs[NB];       // radio_sorted (98 slots; last unused)
    float wb[NB];       // blur_w
    float cdf[NB];      // cdf
    float res[MAXXP];   // interp results
    float pad[2];
};

__device__ __forceinline__ float warpsum(float v) {
    #pragma unroll
    for (int o = 16; o; o >>= 1) v += __shfl_xor_sync(0xffffffffu, v, o);
    return v;
}

// exclusive prefix of per-lane totals
__device__ __forceinline__ float warp_excl_from_total(float tot, int lane) {
    float inc = tot;
    #pragma unroll
    for (int o = 1; o < 32; o <<= 1) {
        float y = __shfl_up_sync(0xffffffffu, inc, o);
        if (lane >= o) inc += y;
    }
    return inc - tot;
}

__global__ void zero_out_kernel(float* out) { out[0] = 0.f; }

__global__ __launch_bounds__(ROWS_PER_BLOCK * 32)
void row_kernel(const float* __restrict__ pd, const float* __restrict__ gt,
                const float* __restrict__ rsd, const float* __restrict__ rw,
                const float* __restrict__ psd0, const float* __restrict__ pwt0,
                const float* __restrict__ psd1, const float* __restrict__ pwt1,
                float* __restrict__ out, int R, int XP0, int XP1)
{
    __shared__ RowS sm[ROWS_PER_BLOCK];
    __shared__ float bacc[ROWS_PER_BLOCK];

    const int warp = threadIdx.x >> 5;
    const int lane = threadIdx.x & 31;
    const int row  = blockIdx.x * ROWS_PER_BLOCK + warp;

    float acc = 0.f;   // per-lane scaled partial (rgb + inter)
    float p1 = 0.f, p2 = 0.f;  // distortion partials (unscaled)

    if (row < R) {
        RowS& S = sm[warp];

        // ---- load sdist, weights, compute wnorm ----
        for (int i = lane; i < NP1; i += 32) S.sd[i] = rsd[row * NP1 + i];
        __syncwarp();
        for (int i = lane; i < NV; i += 32) {
            float wv = rw[row * NV + i];
            S.w[i]  = wv;
            S.wn[i] = wv / (S.sd[i + 1] - S.sd[i] + 1e-8f);
        }
        __syncwarp();

        // ---- rgb loss partial ----
        if (lane < 3) {
            float d = pd[row * 3 + lane] - gt[row * 3 + lane];
            acc += d * d / (3.f * (float)R);
        }

        // ---- distortion loss: part1 = sum_{n,m} w_n w_m |mid_n - mid_m| ----
        for (int n = lane; n < NV; n += 32) {
            float mn = 0.5f * (S.sd[n + 1] + S.sd[n]);
            float wv = S.w[n];
            float inner = 0.f;
            #pragma unroll 4
            for (int m = 0; m < NV; ++m) {
                float mm = 0.5f * (S.sd[m + 1] + S.sd[m]);
                inner += S.w[m] * fabsf(mn - mm);
            }
            p1 += wv * inner;
            p2 += wv * wv * (S.sd[n + 1] - S.sd[n]);
        }

        // ---- interlevel loss, 2 levels ----
        #pragma unroll 1
        for (int lev = 0; lev < 2; ++lev) {
            const float pw = lev ? PW1 : PW0;
            const float* psd = lev ? psd1 : psd0;
            const float* pwt = lev ? pwt1 : pwt0;
            const int XP = lev ? XP1 : XP0;
            const float scale = 1.f / ((float)R * (float)(XP - 1));

            // -- stable merge via rank-scatter --
            for (int p = lane; p < NB; p += 32) {
                float val, rv; int pos;
                if (p < NP1) {
                    val = S.sd[p] - pw;
                    // count of (sd[j]+pw) strictly < val
                    int lo = 0, hi = NP1;
                    while (lo < hi) { int mid = (lo + hi) >> 1;
                        if (S.sd[mid] + pw < val) lo = mid + 1; else hi = mid; }
                    pos = p + lo;
                    float d0 = (p < NV ? S.wn[p] : 0.f) - (p > 0 ? S.wn[p - 1] : 0.f);
                    rv = d0 / (2.f * pw);
                } else {
                    int j = p - NP1;
                    val = S.sd[j] + pw;
                    // count of (sd[i]-pw) <= val
                    int lo = 0, hi = NP1;
                    while (lo < hi) { int mid = (lo + hi) >> 1;
                        if (S.sd[mid] - pw <= val) lo = mid + 1; else hi = mid; }
                    pos = j + lo;
                    float d0 = (j < NV ? S.wn[j] : 0.f) - (j > 0 ? S.wn[j - 1] : 0.f);
                    rv = -d0 / (2.f * pw);
                }
                S.bounds[pos] = val;
                S.rs[pos] = rv;
            }
            __syncwarp();

            // -- three blocked scans over 97 elements (4 per lane) --
            const int base = lane * 4;
            float r4[4], ds4[4];
            #pragma unroll
            for (int t = 0; t < 4; ++t) {
                int k = base + t;
                bool v = (k < NB - 1);
                r4[t]  = v ? S.rs[k] : 0.f;
                ds4[t] = v ? (S.bounds[k + 1] - S.bounds[k]) : 0.f;
            }
            // scan1: cumR = cumsum(radio_sorted)
            float c = 0.f, cum4[4];
            #pragma unroll
            for (int t = 0; t < 4; ++t) { c += r4[t]; cum4[t] = c; }
            float carry1 = warp_excl_from_total(c, lane);
            // prod = ds * cumR; scan2: recover (pre-clamp)
            float c2 = 0.f, rec4[4];
            #pragma unroll
            for (int t = 0; t < 4; ++t) { c2 += ds4[t] * (cum4[t] + carry1); rec4[t] = c2; }
            float carry2 = warp_excl_from_total(c2, lane);
            // w_b[k+1] = max(recover,0); area = 0.5*(wb[k+1]+wb[k])*ds; scan3: cdf
            float c3 = 0.f, cdf4[4], wb4[4];
            float wprev = (base == 0) ? 0.f : fmaxf(carry2, 0.f);
            #pragma unroll
            for (int t = 0; t < 4; ++t) {
                float wbk1 = fmaxf(rec4[t] + carry2, 0.f);
                wb4[t] = wbk1;
                c3 += 0.5f * (wbk1 + wprev) * ds4[t];
                cdf4[t] = c3;
                wprev = wbk1;
            }
            float carry3 = warp_excl_from_total(c3, lane);
            #pragma unroll
            for (int t = 0; t < 4; ++t) {
                int k = base + t;
                if (k < NB - 1) {
                    S.wb[k + 1]  = wb4[t];
                    S.cdf[k + 1] = cdf4[t] + carry3;
                }
            }
            if (lane == 0) { S.wb[0] = 0.f; S.cdf[0] = 0.f; }
            __syncwarp();

            // -- sorted_interp_quad at each prop_sdist point --
            for (int t = lane; t < XP; t += 32) {
                float x = psd[row * XP + t];
                // k = (count of bounds <= x) - 1
                int lo = 0, hi = NB;
                while (lo < hi) { int mid = (lo + hi) >> 1;
                    if (S.bounds[mid] <= x) lo = mid + 1; else hi = mid; }
                int k = lo - 1;
                int kk = k < 0 ? 0 : k;
                float fcdf0 = S.cdf[kk];
                // i0 = first index with cdf >= fcdf0 (argmax-first under ties)
                int l2 = 0, h2 = NB;
                while (l2 < h2) { int mid = (l2 + h2) >> 1;
                    if (S.cdf[mid] < fcdf0) l2 = mid + 1; else h2 = mid; }
                int i0 = l2;
                int i1; float xp0 = S.bounds[kk], xp1;
                if (k < 0)            { i1 = 0; xp1 = S.bounds[0]; }
                else if (k >= NB - 1) { i1 = 0; xp1 = S.bounds[NB - 1]; }
                else {
                    i1 = (S.cdf[k + 1] == S.cdf[NB - 1]) ? 0 : (k + 1);
                    xp1 = S.bounds[k + 1];
                }
                float fp0 = S.wb[i0], fp1 = S.wb[i1];
                float num = x - xp0, den = xp1 - xp0;
                float off = (den > 0.f) ? fminf(fmaxf(num / den, 0.f), 1.f)
                                        : (num > 0.f ? 1.f : 0.f);
                S.res[t] = fcdf0 + num * (fp0 + fp1 * off + fp0 * (1.f - off)) * 0.5f;
            }
            __syncwarp();

            float lsum = 0.f;
            for (int t = lane; t < XP - 1; t += 32) {
                float ws  = S.res[t + 1] - S.res[t];
                float pwv = pwt[row * (XP - 1) + t];
                float d = ws - pwv;
                if (d > 0.f) lsum += d * d / (pwv + 1e-5f);
            }
            acc += lsum * scale;
            __syncwarp();
        }
    }

    // ---- reductions: warp -> block -> one atomicAdd ----
    float wa = warpsum(acc);
    float P1 = warpsum(p1);
    float P2 = warpsum(p2);
    if (lane == 0)
        bacc[warp] = (row < R) ? (wa + (fabsf(P1) + fabsf(P2 * (1.f / 3.f))) * (0.01f / (float)R))
                               : 0.f;
    __syncthreads();
    if (threadIdx.x == 0) {
        float t = 0.f;
        #pragma unroll
        for (int i = 0; i < ROWS_PER_BLOCK; ++i) t += bacc[i];
        atomicAdd(out, t);
    }
}

// hash decay over SORTED indices: run-start threads own a run, no per-segment atomics
__global__ __launch_bounds__(256)
void hash_kernel(const float* __restrict__ emb, const int* __restrict__ idx,
                 float* __restrict__ out, int M, float scale)
{
    int i = blockIdx.x * blockDim.x + threadIdx.x;
    float contrib = 0.f;
    if (i < M) {
        int s = idx[i];
        bool start = (i == 0) || (idx[i - 1] != s);
        if (start) {
            float a2 = 0.f;
            int j = i;
            while (j < M && idx[j] == s) {
                float a = emb[2 * j], b = emb[2 * j + 1];
                a2 += a * a + b * b;
                ++j;
            }
            contrib = a2 / (float)(j - i);   // (s0+s1)/cnt
        }
    }
    contrib = warpsum(contrib);
    __shared__ float sh[8];
    int w = threadIdx.x >> 5, l = threadIdx.x & 31;
    if (l == 0) sh[w] = contrib;
    __syncthreads();
    if (w == 0) {
        float v = (l < 8) ? sh[l] : 0.f;
        v = warpsum(v);
        if (l == 0) atomicAdd(out, v * scale);
    }
}

extern "C" void kernel_launch(void* const* d_in, const int* in_sizes, int n_in,
                              void* d_out, int out_size)
{
    const float* pd   = (const float*)d_in[0];
    const float* gt   = (const float*)d_in[1];
    const float* rsd  = (const float*)d_in[2];
    const float* rw   = (const float*)d_in[3];
    const float* psd0 = (const float*)d_in[4];
    const float* pwt0 = (const float*)d_in[5];
    const float* psd1 = (const float*)d_in[6];
    const float* pwt1 = (const float*)d_in[7];
    const float* emb0 = (const float*)d_in[8];
    const float* emb1 = (const float*)d_in[9];
    const int*   idx0 = (const int*)d_in[10];
    const int*   idx1 = (const int*)d_in[11];
    float* out = (float*)d_out;

    const int R   = in_sizes[0] / 3;          // 4096
    const int XP0 = in_sizes[4] / R;          // 257
    const int XP1 = in_sizes[6] / R;          // 97
    const int M   = in_sizes[8] / 2;          // 196608

    zero_out_kernel<<<1, 1>>>(out);

    const int blocks = (R + ROWS_PER_BLOCK - 1) / ROWS_PER_BLOCK;
    row_kernel<<<blocks, ROWS_PER_BLOCK * 32>>>(pd, gt, rsd, rw,
                                                psd0, pwt0, psd1, pwt1,
                                                out, R, XP0, XP1);

    const float hscale = 0.1f / ((float)NSEG * 2.f);
    hash_kernel<<<(M + 255) / 256, 256>>>(emb0, idx0, out, M, hscale);
    hash_kernel<<<(M + 255) / 256, 256>>>(emb1, idx1, out, M, hscale);
}